// round 12
// baseline (speedup 1.0000x reference)
#include <cuda_runtime.h>
#include <cuda_fp16.h>
#include <cstdint>

#define SEQ    4096
#define DIM    512
#define VOCAB  32000
#define NBLK   4
#define HD2    (2*DIM)
#define CHUNK  64
#define NCH    (SEQ/CHUNK)

// ---- shared GEMM tiling constants ----
#define BM 128
#define BK 64
#define NST 3
#define PITCH 72                        // halves per smem row (64 + 8 pad)
#define A_BYTES (BM*PITCH*2)            // 18432
#define STAGE_B(BNv) ((BNv)*PITCH*2)
#define GSMEM(BNv)   (NST*(A_BYTES + STAGE_B(BNv)))   // BN=256 -> 165888
#define CVPITCH 132                     // floats per smem c/v row (128+4)

// ---------------- scratch (device globals; no allocation allowed) ----------
__device__ float  g_x [SEQ*DIM];
__device__ __half g_xn[SEQ*DIM];
__device__ __half g_xf[SEQ*DIM];        // fp16 raw x for readout A (race-free)
__device__ float  g_rms[SEQ];           // per-row sum of squares
__device__ float  g_P [NCH*DIM];
__device__ float  g_S [NCH*DIM];
__device__ int    g_flag[4*NCH];
__device__ __half g_wt [NBLK*HD2*DIM];          // transposed+interleaved fp16
__device__ __half g_rwt[(size_t)VOCAB*DIM];     // transposed fp16 readout

// ---------------- helpers --------------------------------------------------
__device__ __forceinline__ void cp16(uint32_t saddr, const void* g) {
    asm volatile("cp.async.cg.shared.global [%0], [%1], 16;\n"
                 :: "r"(saddr), "l"(g));
}

__device__ __forceinline__ void ldsm_x4(unsigned* r, uint32_t addr) {
    asm volatile("ldmatrix.sync.aligned.m8n8.x4.shared.b16 {%0,%1,%2,%3}, [%4];"
                 : "=r"(r[0]), "=r"(r[1]), "=r"(r[2]), "=r"(r[3]) : "r"(addr));
}

__device__ __forceinline__ void mma_f16(float* d, const unsigned* a,
                                        const unsigned* b) {
    asm volatile(
        "mma.sync.aligned.m16n8k16.row.col.f32.f16.f16.f32 "
        "{%0,%1,%2,%3}, {%4,%5,%6,%7}, {%8,%9}, {%0,%1,%2,%3};"
        : "+f"(d[0]), "+f"(d[1]), "+f"(d[2]), "+f"(d[3])
        : "r"(a[0]), "r"(a[1]), "r"(a[2]), "r"(a[3]),
          "r"(b[0]), "r"(b[1]));
}

// ---------------- kernels --------------------------------------------------

// Warp-per-row RMSNorm -> fp16. GATHER: fused embedding gather (also fills
// g_x). Also re-zeros scan flags and g_rms (stream-ordered).
template <bool GATHER>
__global__ void __launch_bounds__(128) k_rmsnorm(
        const float* __restrict__ scale,
        const int* __restrict__ ids, const float* __restrict__ emb) {
    if (blockIdx.x < 2)  g_flag[blockIdx.x * 128 + threadIdx.x] = 0;
    if (blockIdx.x < 32) g_rms[blockIdx.x * 128 + threadIdx.x] = 0.0f;

    int warp = threadIdx.x >> 5, lane = threadIdx.x & 31;
    int row  = blockIdx.x * 4 + warp;

    const float4* src = GATHER
        ? (const float4*)(emb + (size_t)ids[row] * DIM)
        : (const float4*)(g_x + (size_t)row * DIM);

    float4 v[4];
    float s = 0.0f;
    #pragma unroll
    for (int j = 0; j < 4; j++) {
        v[j] = src[lane + 32 * j];
        s += v[j].x*v[j].x + v[j].y*v[j].y + v[j].z*v[j].z + v[j].w*v[j].w;
    }
    #pragma unroll
    for (int o = 16; o; o >>= 1) s += __shfl_xor_sync(0xFFFFFFFFu, s, o);
    float r = rsqrtf(s * (1.0f / DIM) + 1e-6f);

    float4* dx  = (float4*)(g_x  + (size_t)row * DIM);
    uint2*  dxn = (uint2*)(g_xn + (size_t)row * DIM);
    #pragma unroll
    for (int j = 0; j < 4; j++) {
        if (GATHER) dx[lane + 32 * j] = v[j];
        float4 sc = ((const float4*)scale)[lane + 32 * j];
        __half2 h0 = __floats2half2_rn(v[j].x * r * sc.x, v[j].y * r * sc.y);
        __half2 h1 = __floats2half2_rn(v[j].z * r * sc.z, v[j].w * r * sc.w);
        uint2 o = {*(unsigned*)&h0, *(unsigned*)&h1};
        dxn[lane + 32 * j] = o;
    }
}

// Transpose + fp16: src [K,N] fp32 -> dst [N',K] fp16.
// inter!=0 remaps output row (hidden/gate interleave). colscale (optional):
// multiply column k by colscale[k] before rounding (folds final_scale).
__global__ void k_transpose(const float* __restrict__ src,
                            __half* __restrict__ dst, int K, int N, int inter,
                            size_t sstride, size_t dstride,
                            const float* __restrict__ colscale) {
    src += blockIdx.z * sstride;
    dst += blockIdx.z * dstride;
    __shared__ float t[32][33];
    int n0 = blockIdx.x * 32, k0 = blockIdx.y * 32;
    int x = threadIdx.x;
    #pragma unroll
    for (int r = threadIdx.y; r < 32; r += 8)
        t[r][x] = src[(size_t)(k0 + r) * N + n0 + x];
    __syncthreads();
    float f = colscale ? colscale[k0 + x] : 1.0f;
    #pragma unroll
    for (int r = threadIdx.y; r < 32; r += 8) {
        int n = n0 + r;
        int nd = inter ? ((n < (N >> 1)) ? 2 * n : 2 * (n - (N >> 1)) + 1) : n;
        dst[(size_t)nd * K + k0 + x] = __float2half_rn(t[x][r] * f);
    }
}

// Readout GEMM: C[M,N] = rowscale(M) * (A[M,K] @ B[N,K]^T), fp32 accum.
// BM=128, BN=256, BK=64, 3-stage cp.async, single-sync, 256 thr,
// warp tile 64x64. Row scale = rsqrt(mean(g_rms)+eps) fused in epilogue.
__global__ void __launch_bounds__(256, 1)
k_gemm_ro(const __half* __restrict__ A, const __half* __restrict__ B,
          float* __restrict__ C, int M, int N, int K) {
    constexpr int BNv = 256;
    constexpr int STG = A_BYTES + STAGE_B(BNv);

    extern __shared__ __half smem[];
    uint32_t sbase = (uint32_t)__cvta_generic_to_shared(smem);

    int tid  = threadIdx.x;
    int lane = tid & 31, warp = tid >> 5;
    int wm = warp & 1;
    int wn = warp >> 1;
    int bRow = blockIdx.y * BM, bCol = blockIdx.x * BNv;

    const __half* Ab = A + (size_t)bRow * K;
    const __half* Bb = B + (size_t)bCol * K;

    float acc[4][8][4];
    #pragma unroll
    for (int mi = 0; mi < 4; mi++)
        #pragma unroll
        for (int ni = 0; ni < 8; ni++)
            #pragma unroll
            for (int r = 0; r < 4; r++) acc[mi][ni][r] = 0.0f;

    auto load_stage = [&](int st, int kt) {
        uint32_t a0 = sbase + st * STG;
        #pragma unroll
        for (int i = 0; i < 4; i++) {
            int f = tid + i * 256;
            int r = f >> 3, c = f & 7;
            cp16(a0 + (r * PITCH + c * 8) * 2, Ab + (size_t)r * K + kt + c * 8);
        }
        uint32_t b0 = a0 + A_BYTES;
        #pragma unroll
        for (int i = 0; i < 8; i++) {
            int f = tid + i * 256;
            int r = f >> 3, c = f & 7;
            cp16(b0 + (r * PITCH + c * 8) * 2, Bb + (size_t)r * K + kt + c * 8);
        }
    };

    int nt = K / BK;

    #pragma unroll
    for (int s = 0; s < NST - 1; s++) {
        load_stage(s, s * BK);
        asm volatile("cp.async.commit_group;" ::: "memory");
    }

    int aRow = wm * 64 + (lane & 15);
    int aCS  = (lane >> 4) * 8;
    int bMat = lane >> 3;
    int bRowOff = (bMat >> 1) * 8 + (lane & 7);
    int bCS  = (bMat & 1) * 8;

    for (int t = 0; t < nt; t++) {
        if (t < nt - 1)
            asm volatile("cp.async.wait_group 1;" ::: "memory");
        else
            asm volatile("cp.async.wait_group 0;" ::: "memory");
        __syncthreads();

        if (t + NST - 1 < nt) {
            load_stage((t + NST - 1) % NST, (t + NST - 1) * BK);
            asm volatile("cp.async.commit_group;" ::: "memory");
        }

        uint32_t As = sbase + (t % NST) * STG;
        uint32_t Bs = As + A_BYTES;

        #pragma unroll
        for (int kk = 0; kk < 4; kk++) {
            int ks = kk * 16;
            unsigned a[4][4], b[4][4];
            #pragma unroll
            for (int mi = 0; mi < 4; mi++)
                ldsm_x4(a[mi], As + ((aRow + mi * 16) * PITCH + ks + aCS) * 2);
            #pragma unroll
            for (int nb = 0; nb < 4; nb++)
                ldsm_x4(b[nb], Bs + ((wn * 64 + nb * 16 + bRowOff) * PITCH
                                     + ks + bCS) * 2);
            #pragma unroll
            for (int mi = 0; mi < 4; mi++)
                #pragma unroll
                for (int ni = 0; ni < 8; ni++)
                    mma_f16(acc[mi][ni], a[mi], &b[ni >> 1][(ni & 1) * 2]);
        }
    }

    int g = lane >> 2, tg = lane & 3;
    #pragma unroll
    for (int mi = 0; mi < 4; mi++) {
        int r0 = bRow + wm * 64 + mi * 16 + g;
        float rs0 = rsqrtf(g_rms[r0]     * (1.0f / DIM) + 1e-6f);
        float rs1 = rsqrtf(g_rms[r0 + 8] * (1.0f / DIM) + 1e-6f);
        #pragma unroll
        for (int ni = 0; ni < 8; ni++) {
            int c0 = bCol + wn * 64 + ni * 8 + 2 * tg;
            float2 lo = {acc[mi][ni][0] * rs0, acc[mi][ni][1] * rs0};
            float2 hi = {acc[mi][ni][2] * rs1, acc[mi][ni][3] * rs1};
            *(float2*)(C + (size_t)r0 * N + c0)       = lo;
            *(float2*)(C + (size_t)(r0 + 8) * N + c0) = hi;
        }
    }
}

// Fused minGRU block: GEMM + gate epilogue (smem) + chunked scan with
// cross-CTA flag chaining. grid (4, 32) = 128 CTAs, 1/SM, all resident.
// LAST: instead of residual into g_x, writes fp16 raw x to g_xf and
// accumulates per-row sum-of-squares into g_rms (warp-reduced atomics).
template <bool LAST>
__global__ void __launch_bounds__(512, 1)
k_block(const __half* __restrict__ A, const __half* __restrict__ B) {
    constexpr int K = DIM;
    constexpr int BNv = 256;
    constexpr int STG = A_BYTES + STAGE_B(BNv);

    extern __shared__ __half smem[];
    uint32_t sbase = (uint32_t)__cvta_generic_to_shared(smem);
    float* sc = (float*)smem;                  // c tile [128][CVPITCH]
    float* sv = sc + 128 * CVPITCH;            // v tile [128][CVPITCH]

    int tid  = threadIdx.x;
    int lane = tid & 31, warp = tid >> 5;
    int wm = warp & 1;
    int wn = warp >> 1;
    int bx = blockIdx.x;               // channel group (0..3)
    int by = blockIdx.y;               // time tile (0..31)
    int bRow = by * BM, bCol = bx * BNv;

    const __half* Ab = A + (size_t)bRow * K;
    const __half* Bb = B + (size_t)bCol * K;

    float acc[4][4][4];
    #pragma unroll
    for (int mi = 0; mi < 4; mi++)
        #pragma unroll
        for (int ni = 0; ni < 4; ni++)
            #pragma unroll
            for (int r = 0; r < 4; r++) acc[mi][ni][r] = 0.0f;

    auto load_stage = [&](int st, int kt) {
        uint32_t a0 = sbase + st * STG;
        #pragma unroll
        for (int i = 0; i < 2; i++) {
            int f = tid + i * 512;
            int r = f >> 3, c = f & 7;
            cp16(a0 + (r * PITCH + c * 8) * 2, Ab + (size_t)r * K + kt + c * 8);
        }
        uint32_t b0 = a0 + A_BYTES;
        #pragma unroll
        for (int i = 0; i < 4; i++) {
            int f = tid + i * 512;
            int r = f >> 3, c = f & 7;
            cp16(b0 + (r * PITCH + c * 8) * 2, Bb + (size_t)r * K + kt + c * 8);
        }
    };

    int nt = K / BK;     // 8

    #pragma unroll
    for (int s = 0; s < NST - 1; s++) {
        load_stage(s, s * BK);
        asm volatile("cp.async.commit_group;" ::: "memory");
    }

    int aRow = wm * 64 + (lane & 15);
    int aCS  = (lane >> 4) * 8;
    int bMat = lane >> 3;
    int bRowOff = (bMat >> 1) * 8 + (lane & 7);
    int bCS  = (bMat & 1) * 8;

    for (int t = 0; t < nt; t++) {
        if (t < nt - 1)
            asm volatile("cp.async.wait_group 1;" ::: "memory");
        else
            asm volatile("cp.async.wait_group 0;" ::: "memory");
        __syncthreads();

        if (t + NST - 1 < nt) {
            load_stage((t + NST - 1) % NST, (t + NST - 1) * BK);
            asm volatile("cp.async.commit_group;" ::: "memory");
        }

        uint32_t As = sbase + (t % NST) * STG;
        uint32_t Bs = As + A_BYTES;

        #pragma unroll
        for (int kk = 0; kk < 4; kk++) {
            int ks = kk * 16;
            unsigned a[4][4], b[2][4];
            #pragma unroll
            for (int mi = 0; mi < 4; mi++)
                ldsm_x4(a[mi], As + ((aRow + mi * 16) * PITCH + ks + aCS) * 2);
            #pragma unroll
            for (int nb = 0; nb < 2; nb++)
                ldsm_x4(b[nb], Bs + ((wn * 32 + nb * 16 + bRowOff) * PITCH
                                     + ks + bCS) * 2);
            #pragma unroll
            for (int mi = 0; mi < 4; mi++)
                #pragma unroll
                for (int ni = 0; ni < 4; ni++)
                    mma_f16(acc[mi][ni], a[mi], &b[ni >> 1][(ni & 1) * 2]);
        }
    }
    __syncthreads();   // all stage smem reads done before c/v overwrite

    // ---- gate epilogue into smem ----
    int g = lane >> 2, tg = lane & 3;
    #pragma unroll
    for (int mi = 0; mi < 4; mi++) {
        int r0 = wm * 64 + mi * 16 + g;
        #pragma unroll
        for (int ni = 0; ni < 4; ni++) {
            int d0 = wn * 16 + ni * 4 + tg;
            #pragma unroll
            for (int h = 0; h < 2; h++) {
                int r = r0 + 8 * h;
                float hd = acc[mi][ni][2 * h];
                float q  = acc[mi][ni][2 * h + 1];
                float eq = __expf(q);
                float cc = 1.0f / (1.0f + eq);
                float z  = eq * cc;
                float gg = hd >= 0.0f ? hd + 0.5f
                                      : 1.0f / (1.0f + __expf(-hd));
                sc[r * CVPITCH + d0] = cc;
                sv[r * CVPITCH + d0] = z * gg;
            }
        }
    }
    __syncthreads();

    // ---- scan: chunks (2by, 2by+1) x channels bx*128.. ----
    int ch = tid >> 7;
    int c  = tid & 127;
    int dglob = bx * 128 + c;

    if (tid < 256) {
        float P = 1.0f, S = 0.0f;
        #pragma unroll 8
        for (int j = 0; j < CHUNK; j++) {
            float cc = sc[(ch * CHUNK + j) * CVPITCH + c];
            float vv = sv[(ch * CHUNK + j) * CVPITCH + c];
            P *= cc;
            S = fmaf(cc, S, vv);
        }
        int CH = 2 * by + ch;
        g_P[CH * DIM + dglob] = P;
        g_S[CH * DIM + dglob] = S;
    }
    __threadfence();
    __syncthreads();
    if (tid == 0) {
        *((volatile int*)&g_flag[bx * NCH + 2 * by])     = 1;
        *((volatile int*)&g_flag[bx * NCH + 2 * by + 1]) = 1;
    }

    if (tid < 2 * by) {
        volatile int* f = &g_flag[bx * NCH + tid];
        while (*f == 0) __nanosleep(40);
    }
    __syncthreads();
    __threadfence();

    if (tid < 256) {
        int CH = 2 * by + ch;
        // MLP-batched cross-chunk combine (8-wide load batches)
        float h = 0.0f;
        int j = 0;
        for (; j + 8 <= CH; j += 8) {
            float p[8], s[8];
            #pragma unroll
            for (int k = 0; k < 8; k++) {
                p[k] = g_P[(j + k) * DIM + dglob];
                s[k] = g_S[(j + k) * DIM + dglob];
            }
            #pragma unroll
            for (int k = 0; k < 8; k++) h = fmaf(p[k], h, s[k]);
        }
        for (; j < CH; j++)
            h = fmaf(g_P[j * DIM + dglob], h, g_S[j * DIM + dglob]);

        #pragma unroll 8
        for (int jj = 0; jj < CHUNK; jj++) {
            float cc = sc[(ch * CHUNK + jj) * CVPITCH + c];
            float vv = sv[(ch * CHUNK + jj) * CVPITCH + c];
            h = fmaf(cc, h, vv);
            int row = CH * CHUNK + jj;
            size_t idx = (size_t)row * DIM + dglob;
            if (LAST) {
                float xn = g_x[idx] + h;
                g_xf[idx] = __float2half_rn(xn);
                float ss = xn * xn;
                #pragma unroll
                for (int o = 16; o; o >>= 1)
                    ss += __shfl_xor_sync(0xFFFFFFFFu, ss, o);
                if (lane == 0) atomicAdd(&g_rms[row], ss);
            } else {
                g_x[idx] += h;
            }
        }
    }
}

// ---------------- host -----------------------------------------------------
extern "C" void kernel_launch(void* const* d_in, const int* in_sizes, int n_in,
                              void* d_out, int out_size) {
    const int*   ids    = (const int*)  d_in[0];
    const float* emb    = (const float*)d_in[1];
    const float* w_hg   = (const float*)d_in[2];
    const float* nscale = (const float*)d_in[3];
    const float* fscale = (const float*)d_in[4];
    const float* rw     = (const float*)d_in[5];
    float*       out    = (float*)d_out;

    static cudaStream_t s2 = nullptr;
    static cudaEvent_t  e1 = nullptr, e2 = nullptr;
    static bool attr_set = false;
    if (!attr_set) {
        cudaFuncSetAttribute(k_block<false>,
                             cudaFuncAttributeMaxDynamicSharedMemorySize, GSMEM(256));
        cudaFuncSetAttribute(k_block<true>,
                             cudaFuncAttributeMaxDynamicSharedMemorySize, GSMEM(256));
        cudaFuncSetAttribute(k_gemm_ro,
                             cudaFuncAttributeMaxDynamicSharedMemorySize, GSMEM(256));
        cudaStreamCreateWithFlags(&s2, cudaStreamNonBlocking);
        cudaEventCreateWithFlags(&e1, cudaEventDisableTiming);
        cudaEventCreateWithFlags(&e2, cudaEventDisableTiming);
        attr_set = true;
    }

    __half *pwt = nullptr, *prwt = nullptr, *pxn = nullptr, *pxf = nullptr;
    cudaGetSymbolAddress((void**)&pxn,  g_xn);
    cudaGetSymbolAddress((void**)&pxf,  g_xf);
    cudaGetSymbolAddress((void**)&pwt,  g_wt);
    cudaGetSymbolAddress((void**)&prwt, g_rwt);

    // readout-weight transpose (fscale folded) on side stream: depends only
    // on inputs; joins before k_gemm_ro. Fills SMs left idle by k_block.
    cudaEventRecord(e1, 0);
    cudaStreamWaitEvent(s2, e1, 0);
    k_transpose<<<dim3(VOCAB / 32, DIM / 32, 1), dim3(32, 8), 0, s2>>>(
        rw, prwt, DIM, VOCAB, 0, 0, 0, fscale);
    cudaEventRecord(e2, s2);

    // block-weight transpose (interleaved) on main stream
    k_transpose<<<dim3(HD2 / 32, DIM / 32, NBLK), dim3(32, 8)>>>(
        w_hg, pwt, DIM, HD2, 1, (size_t)DIM * HD2, (size_t)HD2 * DIM, nullptr);

    for (int i = 0; i < NBLK; i++) {
        if (i == 0)
            k_rmsnorm<true><<<SEQ / 4, 128>>>(nscale, ids, emb);
        else
            k_rmsnorm<false><<<SEQ / 4, 128>>>(nscale + i * DIM, ids, emb);
        if (i < NBLK - 1)
            k_block<false><<<dim3(HD2 / 256, SEQ / BM), 512, GSMEM(256)>>>(
                pxn, pwt + (size_t)i * HD2 * DIM);
        else
            k_block<true><<<dim3(HD2 / 256, SEQ / BM), 512, GSMEM(256)>>>(
                pxn, pwt + (size_t)i * HD2 * DIM);
    }

    cudaStreamWaitEvent(0, e2, 0);
    k_gemm_ro<<<dim3(VOCAB / 256, SEQ / BM), 256, GSMEM(256)>>>(
        pxf, prwt, out, SEQ, VOCAB, DIM);
}

// round 14
// speedup vs baseline: 1.0019x; 1.0019x over previous
#include <cuda_runtime.h>
#include <cuda_fp16.h>
#include <cstdint>

#define SEQ    4096
#define DIM    512
#define VOCAB  32000
#define NBLK   4
#define HD2    (2*DIM)
#define CHUNK  64
#define NCH    (SEQ/CHUNK)

// ---- shared GEMM tiling constants ----
#define BM 128
#define BK 64
#define NST 3
#define PITCH 72                        // halves per smem row (64 + 8 pad)
#define A_BYTES (BM*PITCH*2)            // 18432
#define STAGE_B(BNv) ((BNv)*PITCH*2)
#define GSMEM(BNv)   (NST*(A_BYTES + STAGE_B(BNv)))   // BN=256 -> 165888
#define CVPITCH 132                     // floats per smem c/v row (128+4)

// ---------------- scratch (device globals; no allocation allowed) ----------
__device__ float  g_x [SEQ*DIM];
__device__ __half g_xn[SEQ*DIM];
__device__ __half g_xf[SEQ*DIM];        // fp16 raw x for readout A
__device__ float  g_rms[SEQ];           // per-row sum of squares
__device__ float  g_P [NCH*DIM];
__device__ float  g_S [NCH*DIM];
__device__ int    g_flag[4*NCH];
__device__ __half g_wt [NBLK*HD2*DIM];          // transposed+interleaved fp16
__device__ __half g_rwt[(size_t)VOCAB*DIM];     // transposed fp16 readout

// ---------------- helpers --------------------------------------------------
__device__ __forceinline__ void cp16(uint32_t saddr, const void* g) {
    asm volatile("cp.async.cg.shared.global [%0], [%1], 16;\n"
                 :: "r"(saddr), "l"(g));
}

__device__ __forceinline__ void ldsm_x4(unsigned* r, uint32_t addr) {
    asm volatile("ldmatrix.sync.aligned.m8n8.x4.shared.b16 {%0,%1,%2,%3}, [%4];"
                 : "=r"(r[0]), "=r"(r[1]), "=r"(r[2]), "=r"(r[3]) : "r"(addr));
}

__device__ __forceinline__ void mma_f16(float* d, const unsigned* a,
                                        const unsigned* b) {
    asm volatile(
        "mma.sync.aligned.m16n8k16.row.col.f32.f16.f16.f32 "
        "{%0,%1,%2,%3}, {%4,%5,%6,%7}, {%8,%9}, {%0,%1,%2,%3};"
        : "+f"(d[0]), "+f"(d[1]), "+f"(d[2]), "+f"(d[3])
        : "r"(a[0]), "r"(a[1]), "r"(a[2]), "r"(a[3]),
          "r"(b[0]), "r"(b[1]));
}

// ---------------- kernels --------------------------------------------------

// Warp-per-row RMSNorm -> fp16. GATHER: fused embedding gather (also fills
// g_x). Also re-zeros scan flags and g_rms (stream-ordered).
template <bool GATHER>
__global__ void __launch_bounds__(128) k_rmsnorm(
        const float* __restrict__ scale,
        const int* __restrict__ ids, const float* __restrict__ emb) {
    if (blockIdx.x < 2)  g_flag[blockIdx.x * 128 + threadIdx.x] = 0;
    if (blockIdx.x < 32) g_rms[blockIdx.x * 128 + threadIdx.x] = 0.0f;

    int warp = threadIdx.x >> 5, lane = threadIdx.x & 31;
    int row  = blockIdx.x * 4 + warp;

    const float4* src = GATHER
        ? (const float4*)(emb + (size_t)ids[row] * DIM)
        : (const float4*)(g_x + (size_t)row * DIM);

    float4 v[4];
    float s = 0.0f;
    #pragma unroll
    for (int j = 0; j < 4; j++) {
        v[j] = src[lane + 32 * j];
        s += v[j].x*v[j].x + v[j].y*v[j].y + v[j].z*v[j].z + v[j].w*v[j].w;
    }
    #pragma unroll
    for (int o = 16; o; o >>= 1) s += __shfl_xor_sync(0xFFFFFFFFu, s, o);
    float r = rsqrtf(s * (1.0f / DIM) + 1e-6f);

    float4* dx  = (float4*)(g_x  + (size_t)row * DIM);
    uint2*  dxn = (uint2*)(g_xn + (size_t)row * DIM);
    #pragma unroll
    for (int j = 0; j < 4; j++) {
        if (GATHER) dx[lane + 32 * j] = v[j];
        float4 sc = ((const float4*)scale)[lane + 32 * j];
        __half2 h0 = __floats2half2_rn(v[j].x * r * sc.x, v[j].y * r * sc.y);
        __half2 h1 = __floats2half2_rn(v[j].z * r * sc.z, v[j].w * r * sc.w);
        uint2 o = {*(unsigned*)&h0, *(unsigned*)&h1};
        dxn[lane + 32 * j] = o;
    }
}

// Transpose + fp16: src [K,N] fp32 -> dst [N',K] fp16.
// inter!=0 remaps output row (hidden/gate interleave). colscale (optional):
// multiply column k by colscale[k] before rounding (folds final_scale).
__global__ void k_transpose(const float* __restrict__ src,
                            __half* __restrict__ dst, int K, int N, int inter,
                            size_t sstride, size_t dstride,
                            const float* __restrict__ colscale) {
    src += blockIdx.z * sstride;
    dst += blockIdx.z * dstride;
    __shared__ float t[32][33];
    int n0 = blockIdx.x * 32, k0 = blockIdx.y * 32;
    int x = threadIdx.x;
    #pragma unroll
    for (int r = threadIdx.y; r < 32; r += 8)
        t[r][x] = src[(size_t)(k0 + r) * N + n0 + x];
    __syncthreads();
    float f = colscale ? colscale[k0 + x] : 1.0f;
    #pragma unroll
    for (int r = threadIdx.y; r < 32; r += 8) {
        int n = n0 + r;
        int nd = inter ? ((n < (N >> 1)) ? 2 * n : 2 * (n - (N >> 1)) + 1) : n;
        dst[(size_t)nd * K + k0 + x] = __float2half_rn(t[x][r] * f);
    }
}

// Readout GEMM: C[M,N] = rowscale(M) * (A[M,K] @ B[N,K]^T), fp32 accum.
// BM=128, BN=256, BK=64, 3-stage cp.async, single-sync, 256 thr,
// warp tile 64x64. Row scale = rsqrt(mean(g_rms)+eps) fused in epilogue.
__global__ void __launch_bounds__(256, 1)
k_gemm_ro(const __half* __restrict__ A, const __half* __restrict__ B,
          float* __restrict__ C, int M, int N, int K) {
    constexpr int BNv = 256;
    constexpr int STG = A_BYTES + STAGE_B(BNv);

    extern __shared__ __half smem[];
    uint32_t sbase = (uint32_t)__cvta_generic_to_shared(smem);

    int tid  = threadIdx.x;
    int lane = tid & 31, warp = tid >> 5;
    int wm = warp & 1;
    int wn = warp >> 1;
    int bRow = blockIdx.y * BM, bCol = blockIdx.x * BNv;

    const __half* Ab = A + (size_t)bRow * K;
    const __half* Bb = B + (size_t)bCol * K;

    float acc[4][8][4];
    #pragma unroll
    for (int mi = 0; mi < 4; mi++)
        #pragma unroll
        for (int ni = 0; ni < 8; ni++)
            #pragma unroll
            for (int r = 0; r < 4; r++) acc[mi][ni][r] = 0.0f;

    auto load_stage = [&](int st, int kt) {
        uint32_t a0 = sbase + st * STG;
        #pragma unroll
        for (int i = 0; i < 4; i++) {
            int f = tid + i * 256;
            int r = f >> 3, c = f & 7;
            cp16(a0 + (r * PITCH + c * 8) * 2, Ab + (size_t)r * K + kt + c * 8);
        }
        uint32_t b0 = a0 + A_BYTES;
        #pragma unroll
        for (int i = 0; i < 8; i++) {
            int f = tid + i * 256;
            int r = f >> 3, c = f & 7;
            cp16(b0 + (r * PITCH + c * 8) * 2, Bb + (size_t)r * K + kt + c * 8);
        }
    };

    int nt = K / BK;

    #pragma unroll
    for (int s = 0; s < NST - 1; s++) {
        load_stage(s, s * BK);
        asm volatile("cp.async.commit_group;" ::: "memory");
    }

    int aRow = wm * 64 + (lane & 15);
    int aCS  = (lane >> 4) * 8;
    int bMat = lane >> 3;
    int bRowOff = (bMat >> 1) * 8 + (lane & 7);
    int bCS  = (bMat & 1) * 8;

    for (int t = 0; t < nt; t++) {
        if (t < nt - 1)
            asm volatile("cp.async.wait_group 1;" ::: "memory");
        else
            asm volatile("cp.async.wait_group 0;" ::: "memory");
        __syncthreads();

        if (t + NST - 1 < nt) {
            load_stage((t + NST - 1) % NST, (t + NST - 1) * BK);
            asm volatile("cp.async.commit_group;" ::: "memory");
        }

        uint32_t As = sbase + (t % NST) * STG;
        uint32_t Bs = As + A_BYTES;

        #pragma unroll
        for (int kk = 0; kk < 4; kk++) {
            int ks = kk * 16;
            unsigned a[4][4], b[4][4];
            #pragma unroll
            for (int mi = 0; mi < 4; mi++)
                ldsm_x4(a[mi], As + ((aRow + mi * 16) * PITCH + ks + aCS) * 2);
            #pragma unroll
            for (int nb = 0; nb < 4; nb++)
                ldsm_x4(b[nb], Bs + ((wn * 64 + nb * 16 + bRowOff) * PITCH
                                     + ks + bCS) * 2);
            #pragma unroll
            for (int mi = 0; mi < 4; mi++)
                #pragma unroll
                for (int ni = 0; ni < 8; ni++)
                    mma_f16(acc[mi][ni], a[mi], &b[ni >> 1][(ni & 1) * 2]);
        }
    }

    int g = lane >> 2, tg = lane & 3;
    #pragma unroll
    for (int mi = 0; mi < 4; mi++) {
        int r0 = bRow + wm * 64 + mi * 16 + g;
        float rs0 = rsqrtf(g_rms[r0]     * (1.0f / DIM) + 1e-6f);
        float rs1 = rsqrtf(g_rms[r0 + 8] * (1.0f / DIM) + 1e-6f);
        #pragma unroll
        for (int ni = 0; ni < 8; ni++) {
            int c0 = bCol + wn * 64 + ni * 8 + 2 * tg;
            float2 lo = {acc[mi][ni][0] * rs0, acc[mi][ni][1] * rs0};
            float2 hi = {acc[mi][ni][2] * rs1, acc[mi][ni][3] * rs1};
            *(float2*)(C + (size_t)r0 * N + c0)       = lo;
            *(float2*)(C + (size_t)(r0 + 8) * N + c0) = hi;
        }
    }
}

// Fused minGRU block: GEMM + gate epilogue (smem) + chunked scan with
// cross-CTA flag chaining. grid (4, 32) = 128 CTAs, 1/SM, all resident.
// LAST: writes fp16 raw x to g_xf and accumulates per-row sum-of-squares
// into g_rms instead of the residual-into-g_x path.
template <bool LAST>
__global__ void __launch_bounds__(512, 1)
k_block(const __half* __restrict__ A, const __half* __restrict__ B) {
    constexpr int K = DIM;
    constexpr int BNv = 256;
    constexpr int STG = A_BYTES + STAGE_B(BNv);

    extern __shared__ __half smem[];
    uint32_t sbase = (uint32_t)__cvta_generic_to_shared(smem);
    float* sc = (float*)smem;                  // c tile [128][CVPITCH]
    float* sv = sc + 128 * CVPITCH;            // v tile [128][CVPITCH]

    int tid  = threadIdx.x;
    int lane = tid & 31, warp = tid >> 5;
    int wm = warp & 1;
    int wn = warp >> 1;
    int bx = blockIdx.x;               // channel group (0..3)
    int by = blockIdx.y;               // time tile (0..31)
    int bRow = by * BM, bCol = bx * BNv;

    const __half* Ab = A + (size_t)bRow * K;
    const __half* Bb = B + (size_t)bCol * K;

    float acc[4][4][4];
    #pragma unroll
    for (int mi = 0; mi < 4; mi++)
        #pragma unroll
        for (int ni = 0; ni < 4; ni++)
            #pragma unroll
            for (int r = 0; r < 4; r++) acc[mi][ni][r] = 0.0f;

    auto load_stage = [&](int st, int kt) {
        uint32_t a0 = sbase + st * STG;
        #pragma unroll
        for (int i = 0; i < 2; i++) {
            int f = tid + i * 512;
            int r = f >> 3, c = f & 7;
            cp16(a0 + (r * PITCH + c * 8) * 2, Ab + (size_t)r * K + kt + c * 8);
        }
        uint32_t b0 = a0 + A_BYTES;
        #pragma unroll
        for (int i = 0; i < 4; i++) {
            int f = tid + i * 512;
            int r = f >> 3, c = f & 7;
            cp16(b0 + (r * PITCH + c * 8) * 2, Bb + (size_t)r * K + kt + c * 8);
        }
    };

    int nt = K / BK;     // 8

    #pragma unroll
    for (int s = 0; s < NST - 1; s++) {
        load_stage(s, s * BK);
        asm volatile("cp.async.commit_group;" ::: "memory");
    }

    int aRow = wm * 64 + (lane & 15);
    int aCS  = (lane >> 4) * 8;
    int bMat = lane >> 3;
    int bRowOff = (bMat >> 1) * 8 + (lane & 7);
    int bCS  = (bMat & 1) * 8;

    for (int t = 0; t < nt; t++) {
        if (t < nt - 1)
            asm volatile("cp.async.wait_group 1;" ::: "memory");
        else
            asm volatile("cp.async.wait_group 0;" ::: "memory");
        __syncthreads();

        if (t + NST - 1 < nt) {
            load_stage((t + NST - 1) % NST, (t + NST - 1) * BK);
            asm volatile("cp.async.commit_group;" ::: "memory");
        }

        uint32_t As = sbase + (t % NST) * STG;
        uint32_t Bs = As + A_BYTES;

        #pragma unroll
        for (int kk = 0; kk < 4; kk++) {
            int ks = kk * 16;
            unsigned a[4][4], b[2][4];
            #pragma unroll
            for (int mi = 0; mi < 4; mi++)
                ldsm_x4(a[mi], As + ((aRow + mi * 16) * PITCH + ks + aCS) * 2);
            #pragma unroll
            for (int nb = 0; nb < 2; nb++)
                ldsm_x4(b[nb], Bs + ((wn * 32 + nb * 16 + bRowOff) * PITCH
                                     + ks + bCS) * 2);
            #pragma unroll
            for (int mi = 0; mi < 4; mi++)
                #pragma unroll
                for (int ni = 0; ni < 4; ni++)
                    mma_f16(acc[mi][ni], a[mi], &b[ni >> 1][(ni & 1) * 2]);
        }
    }
    __syncthreads();   // all stage smem reads done before c/v overwrite

    // ---- gate epilogue into smem ----
    int g = lane >> 2, tg = lane & 3;
    #pragma unroll
    for (int mi = 0; mi < 4; mi++) {
        int r0 = wm * 64 + mi * 16 + g;
        #pragma unroll
        for (int ni = 0; ni < 4; ni++) {
            int d0 = wn * 16 + ni * 4 + tg;
            #pragma unroll
            for (int h = 0; h < 2; h++) {
                int r = r0 + 8 * h;
                float hd = acc[mi][ni][2 * h];
                float q  = acc[mi][ni][2 * h + 1];
                float eq = __expf(q);
                float cc = 1.0f / (1.0f + eq);
                float z  = eq * cc;
                float gg = hd >= 0.0f ? hd + 0.5f
                                      : 1.0f / (1.0f + __expf(-hd));
                sc[r * CVPITCH + d0] = cc;
                sv[r * CVPITCH + d0] = z * gg;
            }
        }
    }
    __syncthreads();

    // ---- scan: chunks (2by, 2by+1) x channels bx*128.. ----
    int ch = tid >> 7;
    int c  = tid & 127;
    int dglob = bx * 128 + c;

    if (tid < 256) {
        float P = 1.0f, S = 0.0f;
        #pragma unroll 8
        for (int j = 0; j < CHUNK; j++) {
            float cc = sc[(ch * CHUNK + j) * CVPITCH + c];
            float vv = sv[(ch * CHUNK + j) * CVPITCH + c];
            P *= cc;
            S = fmaf(cc, S, vv);
        }
        int CH = 2 * by + ch;
        g_P[CH * DIM + dglob] = P;
        g_S[CH * DIM + dglob] = S;
    }
    __threadfence();
    __syncthreads();
    if (tid == 0) {
        *((volatile int*)&g_flag[bx * NCH + 2 * by])     = 1;
        *((volatile int*)&g_flag[bx * NCH + 2 * by + 1]) = 1;
    }

    if (tid < 2 * by) {
        volatile int* f = &g_flag[bx * NCH + tid];
        while (*f == 0) __nanosleep(40);
    }
    __syncthreads();
    __threadfence();

    if (tid < 256) {
        int CH = 2 * by + ch;
        float h = 0.0f;
        for (int j = 0; j < CH; j++)
            h = fmaf(g_P[j * DIM + dglob], h, g_S[j * DIM + dglob]);

        #pragma unroll 8
        for (int jj = 0; jj < CHUNK; jj++) {
            float cc = sc[(ch * CHUNK + jj) * CVPITCH + c];
            float vv = sv[(ch * CHUNK + jj) * CVPITCH + c];
            h = fmaf(cc, h, vv);
            int row = CH * CHUNK + jj;
            size_t idx = (size_t)row * DIM + dglob;
            if (LAST) {
                float xn = g_x[idx] + h;
                g_xf[idx] = __float2half_rn(xn);
                float ss = xn * xn;
                #pragma unroll
                for (int o = 16; o; o >>= 1)
                    ss += __shfl_xor_sync(0xFFFFFFFFu, ss, o);
                if (lane == 0) atomicAdd(&g_rms[row], ss);
            } else {
                g_x[idx] += h;
            }
        }
    }
}

// ---------------- host -----------------------------------------------------
extern "C" void kernel_launch(void* const* d_in, const int* in_sizes, int n_in,
                              void* d_out, int out_size) {
    const int*   ids    = (const int*)  d_in[0];
    const float* emb    = (const float*)d_in[1];
    const float* w_hg   = (const float*)d_in[2];
    const float* nscale = (const float*)d_in[3];
    const float* fscale = (const float*)d_in[4];
    const float* rw     = (const float*)d_in[5];
    float*       out    = (float*)d_out;

    static bool attr_set = false;
    if (!attr_set) {
        cudaFuncSetAttribute(k_block<false>,
                             cudaFuncAttributeMaxDynamicSharedMemorySize, GSMEM(256));
        cudaFuncSetAttribute(k_block<true>,
                             cudaFuncAttributeMaxDynamicSharedMemorySize, GSMEM(256));
        cudaFuncSetAttribute(k_gemm_ro,
                             cudaFuncAttributeMaxDynamicSharedMemorySize, GSMEM(256));
        attr_set = true;
    }

    __half *pwt = nullptr, *prwt = nullptr, *pxn = nullptr, *pxf = nullptr;
    cudaGetSymbolAddress((void**)&pxn,  g_xn);
    cudaGetSymbolAddress((void**)&pxf,  g_xf);
    cudaGetSymbolAddress((void**)&pwt,  g_wt);
    cudaGetSymbolAddress((void**)&prwt, g_rwt);

    // prepass (single stream; no overlap with the resident-dependent
    // k_block): block weights interleaved, readout weights fscale-folded
    k_transpose<<<dim3(HD2 / 32, DIM / 32, NBLK), dim3(32, 8)>>>(
        w_hg, pwt, DIM, HD2, 1, (size_t)DIM * HD2, (size_t)HD2 * DIM, nullptr);
    k_transpose<<<dim3(VOCAB / 32, DIM / 32, 1), dim3(32, 8)>>>(
        rw, prwt, DIM, VOCAB, 0, 0, 0, fscale);

    for (int i = 0; i < NBLK; i++) {
        if (i == 0)
            k_rmsnorm<true><<<SEQ / 4, 128>>>(nscale, ids, emb);
        else
            k_rmsnorm<false><<<SEQ / 4, 128>>>(nscale + i * DIM, ids, emb);
        if (i < NBLK - 1)
            k_block<false><<<dim3(HD2 / 256, SEQ / BM), 512, GSMEM(256)>>>(
                pxn, pwt + (size_t)i * HD2 * DIM);
        else
            k_block<true><<<dim3(HD2 / 256, SEQ / BM), 512, GSMEM(256)>>>(
                pxn, pwt + (size_t)i * HD2 * DIM);
    }

    k_gemm_ro<<<dim3(VOCAB / 256, SEQ / BM), 256, GSMEM(256)>>>(
        pxf, prwt, out, SEQ, VOCAB, DIM);
}

// round 15
// speedup vs baseline: 1.0624x; 1.0604x over previous
#include <cuda_runtime.h>
#include <cuda_fp16.h>
#include <cstdint>

#define SEQ    4096
#define DIM    512
#define VOCAB  32000
#define NBLK   4
#define HD2    (2*DIM)
#define CHUNK  64
#define NCH    (SEQ/CHUNK)

// ---- shared GEMM tiling constants ----
#define BM 128
#define BK 64
#define NST 3
#define PITCH 72                        // halves per smem row (64 + 8 pad)
#define A_BYTES (BM*PITCH*2)            // 18432
#define STAGE_B(BNv) ((BNv)*PITCH*2)
#define GSMEM(BNv)   (NST*(A_BYTES + STAGE_B(BNv)))   // BN=256 -> 165888
#define CVPITCH 132                     // floats per smem c/v row (128+4)
#define CV_BYTES (2*128*CVPITCH*4)      // 135168 (sc+sv)

// ---------------- scratch (device globals; no allocation allowed) ----------
__device__ float  g_x [SEQ*DIM];
__device__ __half g_xn[SEQ*DIM];
__device__ float  g_P [NCH*DIM];
__device__ float  g_S [NCH*DIM];
__device__ int    g_flag[4*NCH];
__device__ __half g_wt [NBLK*HD2*DIM];          // transposed+interleaved fp16
__device__ __half g_rwt[(size_t)VOCAB*DIM];     // transposed fp16 readout

// ---------------- helpers --------------------------------------------------
__device__ __forceinline__ void cp16(uint32_t saddr, const void* g) {
    asm volatile("cp.async.cg.shared.global [%0], [%1], 16;\n"
                 :: "r"(saddr), "l"(g));
}

__device__ __forceinline__ void ldsm_x4(unsigned* r, uint32_t addr) {
    asm volatile("ldmatrix.sync.aligned.m8n8.x4.shared.b16 {%0,%1,%2,%3}, [%4];"
                 : "=r"(r[0]), "=r"(r[1]), "=r"(r[2]), "=r"(r[3]) : "r"(addr));
}

__device__ __forceinline__ void mma_f16(float* d, const unsigned* a,
                                        const unsigned* b) {
    asm volatile(
        "mma.sync.aligned.m16n8k16.row.col.f32.f16.f16.f32 "
        "{%0,%1,%2,%3}, {%4,%5,%6,%7}, {%8,%9}, {%0,%1,%2,%3};"
        : "+f"(d[0]), "+f"(d[1]), "+f"(d[2]), "+f"(d[3])
        : "r"(a[0]), "r"(a[1]), "r"(a[2]), "r"(a[3]),
          "r"(b[0]), "r"(b[1]));
}

// ---------------- kernels --------------------------------------------------

// Warp-per-row RMSNorm -> fp16. GATHER: fused embedding gather (also fills
// g_x). Also re-zeros scan flags (stream-ordered before the next k_block).
template <bool GATHER>
__global__ void __launch_bounds__(128) k_rmsnorm(
        const float* __restrict__ scale,
        const int* __restrict__ ids, const float* __restrict__ emb) {
    if (blockIdx.x < 2) g_flag[blockIdx.x * 128 + threadIdx.x] = 0;

    int warp = threadIdx.x >> 5, lane = threadIdx.x & 31;
    int row  = blockIdx.x * 4 + warp;

    const float4* src = GATHER
        ? (const float4*)(emb + (size_t)ids[row] * DIM)
        : (const float4*)(g_x + (size_t)row * DIM);

    float4 v[4];
    float s = 0.0f;
    #pragma unroll
    for (int j = 0; j < 4; j++) {
        v[j] = src[lane + 32 * j];
        s += v[j].x*v[j].x + v[j].y*v[j].y + v[j].z*v[j].z + v[j].w*v[j].w;
    }
    #pragma unroll
    for (int o = 16; o; o >>= 1) s += __shfl_xor_sync(0xFFFFFFFFu, s, o);
    float r = rsqrtf(s * (1.0f / DIM) + 1e-6f);

    float4* dx  = (float4*)(g_x  + (size_t)row * DIM);
    uint2*  dxn = (uint2*)(g_xn + (size_t)row * DIM);
    #pragma unroll
    for (int j = 0; j < 4; j++) {
        if (GATHER) dx[lane + 32 * j] = v[j];
        float4 sc = ((const float4*)scale)[lane + 32 * j];
        __half2 h0 = __floats2half2_rn(v[j].x * r * sc.x, v[j].y * r * sc.y);
        __half2 h1 = __floats2half2_rn(v[j].z * r * sc.z, v[j].w * r * sc.w);
        uint2 o = {*(unsigned*)&h0, *(unsigned*)&h1};
        dxn[lane + 32 * j] = o;
    }
}

// Transpose + fp16: src [K,N] fp32 -> dst [N',K] fp16.
// inter!=0 remaps output row: n<N/2 -> 2n (hidden), else 2(n-N/2)+1 (gate).
__global__ void k_transpose(const float* __restrict__ src,
                            __half* __restrict__ dst, int K, int N, int inter,
                            size_t sstride, size_t dstride) {
    src += blockIdx.z * sstride;
    dst += blockIdx.z * dstride;
    __shared__ float t[32][33];
    int n0 = blockIdx.x * 32, k0 = blockIdx.y * 32;
    int x = threadIdx.x;
    #pragma unroll
    for (int r = threadIdx.y; r < 32; r += 8)
        t[r][x] = src[(size_t)(k0 + r) * N + n0 + x];
    __syncthreads();
    #pragma unroll
    for (int r = threadIdx.y; r < 32; r += 8) {
        int n = n0 + r;
        int nd = inter ? ((n < (N >> 1)) ? 2 * n : 2 * (n - (N >> 1)) + 1) : n;
        dst[(size_t)nd * K + k0 + x] = __float2half_rn(t[x][r]);
    }
}

// Readout GEMM: C[M,N] = A[M,K] @ B[N,K]^T, fp32 accum. BM=128, BN=256,
// BK=64, 3-stage cp.async, single-sync, 256 thr, warp tile 64x64.
__global__ void __launch_bounds__(256, 1)
k_gemm_ro(const __half* __restrict__ A, const __half* __restrict__ B,
          float* __restrict__ C, int M, int N, int K) {
    constexpr int BNv = 256;
    constexpr int STG = A_BYTES + STAGE_B(BNv);

    extern __shared__ __half smem[];
    uint32_t sbase = (uint32_t)__cvta_generic_to_shared(smem);

    int tid  = threadIdx.x;
    int lane = tid & 31, warp = tid >> 5;
    int wm = warp & 1;
    int wn = warp >> 1;
    int bRow = blockIdx.y * BM, bCol = blockIdx.x * BNv;

    const __half* Ab = A + (size_t)bRow * K;
    const __half* Bb = B + (size_t)bCol * K;

    float acc[4][8][4];
    #pragma unroll
    for (int mi = 0; mi < 4; mi++)
        #pragma unroll
        for (int ni = 0; ni < 8; ni++)
            #pragma unroll
            for (int r = 0; r < 4; r++) acc[mi][ni][r] = 0.0f;

    auto load_stage = [&](int st, int kt) {
        uint32_t a0 = sbase + st * STG;
        #pragma unroll
        for (int i = 0; i < 4; i++) {
            int f = tid + i * 256;
            int r = f >> 3, c = f & 7;
            cp16(a0 + (r * PITCH + c * 8) * 2, Ab + (size_t)r * K + kt + c * 8);
        }
        uint32_t b0 = a0 + A_BYTES;
        #pragma unroll
        for (int i = 0; i < 8; i++) {
            int f = tid + i * 256;
            int r = f >> 3, c = f & 7;
            cp16(b0 + (r * PITCH + c * 8) * 2, Bb + (size_t)r * K + kt + c * 8);
        }
    };

    int nt = K / BK;

    #pragma unroll
    for (int s = 0; s < NST - 1; s++) {
        load_stage(s, s * BK);
        asm volatile("cp.async.commit_group;" ::: "memory");
    }

    int aRow = wm * 64 + (lane & 15);
    int aCS  = (lane >> 4) * 8;
    int bMat = lane >> 3;
    int bRowOff = (bMat >> 1) * 8 + (lane & 7);
    int bCS  = (bMat & 1) * 8;

    for (int t = 0; t < nt; t++) {
        if (t < nt - 1)
            asm volatile("cp.async.wait_group 1;" ::: "memory");
        else
            asm volatile("cp.async.wait_group 0;" ::: "memory");
        __syncthreads();

        if (t + NST - 1 < nt) {
            load_stage((t + NST - 1) % NST, (t + NST - 1) * BK);
            asm volatile("cp.async.commit_group;" ::: "memory");
        }

        uint32_t As = sbase + (t % NST) * STG;
        uint32_t Bs = As + A_BYTES;

        #pragma unroll
        for (int kk = 0; kk < 4; kk++) {
            int ks = kk * 16;
            unsigned a[4][4], b[4][4];
            #pragma unroll
            for (int mi = 0; mi < 4; mi++)
                ldsm_x4(a[mi], As + ((aRow + mi * 16) * PITCH + ks + aCS) * 2);
            #pragma unroll
            for (int nb = 0; nb < 4; nb++)
                ldsm_x4(b[nb], Bs + ((wn * 64 + nb * 16 + bRowOff) * PITCH
                                     + ks + bCS) * 2);
            #pragma unroll
            for (int mi = 0; mi < 4; mi++)
                #pragma unroll
                for (int ni = 0; ni < 8; ni++)
                    mma_f16(acc[mi][ni], a[mi], &b[ni >> 1][(ni & 1) * 2]);
        }
    }

    int g = lane >> 2, tg = lane & 3;
    #pragma unroll
    for (int mi = 0; mi < 4; mi++) {
        int r0 = bRow + wm * 64 + mi * 16 + g;
        #pragma unroll
        for (int ni = 0; ni < 8; ni++) {
            int c0 = bCol + wn * 64 + ni * 8 + 2 * tg;
            float2 lo = {acc[mi][ni][0], acc[mi][ni][1]};
            float2 hi = {acc[mi][ni][2], acc[mi][ni][3]};
            *(float2*)(C + (size_t)r0 * N + c0)       = lo;
            *(float2*)(C + (size_t)(r0 + 8) * N + c0) = hi;
        }
    }
}

// Fused minGRU block: GEMM + gate epilogue (smem) + SPLIT chunked scan.
// grid (4, 32) = 128 CTAs, 1/SM, all resident -> flag spin deadlock-free.
// Scan uses all 512 threads: each (chunk, channel) column is handled by a
// thread PAIR splitting the 64 time steps into two 32-step halves.
__global__ void __launch_bounds__(512, 1)
k_block(const __half* __restrict__ A, const __half* __restrict__ B) {
    constexpr int K = DIM;
    constexpr int BNv = 256;
    constexpr int STG = A_BYTES + STAGE_B(BNv);

    extern __shared__ __half smem[];
    uint32_t sbase = (uint32_t)__cvta_generic_to_shared(smem);
    float* sc = (float*)smem;                  // c tile [128][CVPITCH]
    float* sv = sc + 128 * CVPITCH;            // v tile [128][CVPITCH]
    float* sPp  = (float*)((char*)smem + CV_BYTES);  // [2(half)][2(ch)][128]
    float* sSp  = sPp + 512;                          // [2][2][128]
    float* sHin = sSp + 512;                          // [2][128]

    int tid  = threadIdx.x;
    int lane = tid & 31, warp = tid >> 5;
    int wm = warp & 1;
    int wn = warp >> 1;
    int bx = blockIdx.x;               // channel group (0..3)
    int by = blockIdx.y;               // time tile (0..31)
    int bRow = by * BM, bCol = bx * BNv;

    const __half* Ab = A + (size_t)bRow * K;
    const __half* Bb = B + (size_t)bCol * K;

    float acc[4][4][4];
    #pragma unroll
    for (int mi = 0; mi < 4; mi++)
        #pragma unroll
        for (int ni = 0; ni < 4; ni++)
            #pragma unroll
            for (int r = 0; r < 4; r++) acc[mi][ni][r] = 0.0f;

    auto load_stage = [&](int st, int kt) {
        uint32_t a0 = sbase + st * STG;
        #pragma unroll
        for (int i = 0; i < 2; i++) {
            int f = tid + i * 512;
            int r = f >> 3, c = f & 7;
            cp16(a0 + (r * PITCH + c * 8) * 2, Ab + (size_t)r * K + kt + c * 8);
        }
        uint32_t b0 = a0 + A_BYTES;
        #pragma unroll
        for (int i = 0; i < 4; i++) {
            int f = tid + i * 512;
            int r = f >> 3, c = f & 7;
            cp16(b0 + (r * PITCH + c * 8) * 2, Bb + (size_t)r * K + kt + c * 8);
        }
    };

    int nt = K / BK;     // 8

    #pragma unroll
    for (int s = 0; s < NST - 1; s++) {
        load_stage(s, s * BK);
        asm volatile("cp.async.commit_group;" ::: "memory");
    }

    int aRow = wm * 64 + (lane & 15);
    int aCS  = (lane >> 4) * 8;
    int bMat = lane >> 3;
    int bRowOff = (bMat >> 1) * 8 + (lane & 7);
    int bCS  = (bMat & 1) * 8;

    for (int t = 0; t < nt; t++) {
        if (t < nt - 1)
            asm volatile("cp.async.wait_group 1;" ::: "memory");
        else
            asm volatile("cp.async.wait_group 0;" ::: "memory");
        __syncthreads();

        if (t + NST - 1 < nt) {
            load_stage((t + NST - 1) % NST, (t + NST - 1) * BK);
            asm volatile("cp.async.commit_group;" ::: "memory");
        }

        uint32_t As = sbase + (t % NST) * STG;
        uint32_t Bs = As + A_BYTES;

        #pragma unroll
        for (int kk = 0; kk < 4; kk++) {
            int ks = kk * 16;
            unsigned a[4][4], b[2][4];
            #pragma unroll
            for (int mi = 0; mi < 4; mi++)
                ldsm_x4(a[mi], As + ((aRow + mi * 16) * PITCH + ks + aCS) * 2);
            #pragma unroll
            for (int nb = 0; nb < 2; nb++)
                ldsm_x4(b[nb], Bs + ((wn * 32 + nb * 16 + bRowOff) * PITCH
                                     + ks + bCS) * 2);
            #pragma unroll
            for (int mi = 0; mi < 4; mi++)
                #pragma unroll
                for (int ni = 0; ni < 4; ni++)
                    mma_f16(acc[mi][ni], a[mi], &b[ni >> 1][(ni & 1) * 2]);
        }
    }
    __syncthreads();   // all stage smem reads done before c/v overwrite

    // ---- gate epilogue into smem ----
    int g = lane >> 2, tg = lane & 3;
    #pragma unroll
    for (int mi = 0; mi < 4; mi++) {
        int r0 = wm * 64 + mi * 16 + g;
        #pragma unroll
        for (int ni = 0; ni < 4; ni++) {
            int d0 = wn * 16 + ni * 4 + tg;
            #pragma unroll
            for (int h = 0; h < 2; h++) {
                int r = r0 + 8 * h;
                float hd = acc[mi][ni][2 * h];
                float q  = acc[mi][ni][2 * h + 1];
                float eq = __expf(q);
                float cc = 1.0f / (1.0f + eq);
                float z  = eq * cc;
                float gg = hd >= 0.0f ? hd + 0.5f
                                      : 1.0f / (1.0f + __expf(-hd));
                sc[r * CVPITCH + d0] = cc;
                sv[r * CVPITCH + d0] = z * gg;
            }
        }
    }
    __syncthreads();

    // ---- split scan: thread pair per (chunk, channel) column ----
    int half = tid >> 8;               // 0: steps [0,32), 1: steps [32,64)
    int ch   = (tid >> 7) & 1;         // chunk within tile
    int c    = tid & 127;              // channel within group
    int dglob = bx * 128 + c;
    int tbase = ch * CHUNK + half * 32;

    // phase 1: 32-step half partials (all 512 threads)
    float Ph = 1.0f, Sh = 0.0f;
    #pragma unroll 8
    for (int j = 0; j < 32; j++) {
        float cc = sc[(tbase + j) * CVPITCH + c];
        float vv = sv[(tbase + j) * CVPITCH + c];
        Ph *= cc;
        Sh = fmaf(cc, Sh, vv);
    }
    sPp[(half * 2 + ch) * 128 + c] = Ph;
    sSp[(half * 2 + ch) * 128 + c] = Sh;
    __syncthreads();

    // phase 2: combine halves, publish chunk partials (threads 0..255)
    if (tid < 256) {
        float P1 = sPp[(2 + ch) * 128 + c];
        float S1 = sSp[(2 + ch) * 128 + c];
        int CH = 2 * by + ch;
        g_P[CH * DIM + dglob] = Ph * P1;             // Ph,Sh are half-0 here
        g_S[CH * DIM + dglob] = fmaf(P1, Sh, S1);
    }
    __threadfence();
    __syncthreads();
    if (tid < 2)
        *((volatile int*)&g_flag[bx * NCH + 2 * by + tid]) = 1;

    // spin on predecessor chunks (< 2*by) of this channel group
    if (tid < 2 * by) {
        volatile int* f = &g_flag[bx * NCH + tid];
        while (*f == 0) __nanosleep(40);
    }
    __syncthreads();
    __threadfence();

    // phase 3: incoming h per chunk (threads 0..255)
    if (tid < 256) {
        int CH = 2 * by + ch;
        float h = 0.0f;
        for (int j = 0; j < CH; j++)
            h = fmaf(g_P[j * DIM + dglob], h, g_S[j * DIM + dglob]);
        sHin[ch * 128 + c] = h;
    }
    __syncthreads();

    // phase 4: apply 32 steps + residual (all 512 threads)
    float h = sHin[ch * 128 + c];
    if (half) {
        float P0 = sPp[(0 * 2 + ch) * 128 + c];
        float S0 = sSp[(0 * 2 + ch) * 128 + c];
        h = fmaf(P0, h, S0);
    }
    int rbase = (2 * by + ch) * CHUNK + half * 32;
    #pragma unroll 8
    for (int j = 0; j < 32; j++) {
        float cc = sc[(tbase + j) * CVPITCH + c];
        float vv = sv[(tbase + j) * CVPITCH + c];
        h = fmaf(cc, h, vv);
        g_x[(size_t)(rbase + j) * DIM + dglob] += h;
    }
}

// ---------------- host -----------------------------------------------------
extern "C" void kernel_launch(void* const* d_in, const int* in_sizes, int n_in,
                              void* d_out, int out_size) {
    const int*   ids    = (const int*)  d_in[0];
    const float* emb    = (const float*)d_in[1];
    const float* w_hg   = (const float*)d_in[2];
    const float* nscale = (const float*)d_in[3];
    const float* fscale = (const float*)d_in[4];
    const float* rw     = (const float*)d_in[5];
    float*       out    = (float*)d_out;

    static bool attr_set = false;
    if (!attr_set) {
        cudaFuncSetAttribute(k_block,
                             cudaFuncAttributeMaxDynamicSharedMemorySize, GSMEM(256));
        cudaFuncSetAttribute(k_gemm_ro,
                             cudaFuncAttributeMaxDynamicSharedMemorySize, GSMEM(256));
        attr_set = true;
    }

    __half *pwt = nullptr, *prwt = nullptr, *pxn = nullptr;
    cudaGetSymbolAddress((void**)&pxn,  g_xn);
    cudaGetSymbolAddress((void**)&pwt,  g_wt);
    cudaGetSymbolAddress((void**)&prwt, g_rwt);

    // prepass (single stream): block weights interleaved, readout plain
    k_transpose<<<dim3(HD2 / 32, DIM / 32, NBLK), dim3(32, 8)>>>(
        w_hg, pwt, DIM, HD2, 1, (size_t)DIM * HD2, (size_t)HD2 * DIM);
    k_transpose<<<dim3(VOCAB / 32, DIM / 32, 1), dim3(32, 8)>>>(
        rw, prwt, DIM, VOCAB, 0, 0, 0);

    for (int i = 0; i < NBLK; i++) {
        if (i == 0)
            k_rmsnorm<true><<<SEQ / 4, 128>>>(nscale, ids, emb);
        else
            k_rmsnorm<false><<<SEQ / 4, 128>>>(nscale + i * DIM, ids, emb);
        k_block<<<dim3(HD2 / 256, SEQ / BM), 512, GSMEM(256)>>>(
            pxn, pwt + (size_t)i * HD2 * DIM);
    }

    k_rmsnorm<false><<<SEQ / 4, 128>>>(fscale, ids, emb);
    k_gemm_ro<<<dim3(VOCAB / 256, SEQ / BM), 256, GSMEM(256)>>>(
        pxn, prwt, out, SEQ, VOCAB, DIM);
}